// round 5
// baseline (speedup 1.0000x reference)
#include <cuda_runtime.h>
#include <cuda_bf16.h>
#include <cstdint>

// ---------------------------------------------------------------------------
// x[65536,512] -> qkv = x @ qkv_w^T -> windowed attn (1024x8, 64x64x64)
//   -> out = att @ proj_w^T + b
// GEMMs: HMMA bf16 3-term hi/lo split, 2-stage cp.async pipeline (BK=32).
// Attention: fp32 with FMA-pipe polynomial exp (MUFU was the bottleneck).
// ---------------------------------------------------------------------------

#define M_ROWS   65536
#define C_DIM    512
#define QKV_DIM  1536
#define NH       8
#define HD       64
#define WINW     64
#define NWIN     1024

__device__ float         g_qkv[(long long)M_ROWS * QKV_DIM];
__device__ __nv_bfloat16 g_xh [(long long)M_ROWS * C_DIM];
__device__ __nv_bfloat16 g_xl [(long long)M_ROWS * C_DIM];
__device__ __nv_bfloat16 g_ath[(long long)M_ROWS * C_DIM];
__device__ __nv_bfloat16 g_atl[(long long)M_ROWS * C_DIM];
__device__ __nv_bfloat16 g_wqh[QKV_DIM * C_DIM];
__device__ __nv_bfloat16 g_wql[QKV_DIM * C_DIM];
__device__ __nv_bfloat16 g_wph[C_DIM * C_DIM];
__device__ __nv_bfloat16 g_wpl[C_DIM * C_DIM];

// ------------------------------ helpers ------------------------------------
__device__ __forceinline__ uint32_t smem_u32(const void* p) {
    uint32_t a;
    asm("{ .reg .u64 t; cvta.to.shared.u64 t, %1; cvt.u32.u64 %0, t; }"
        : "=r"(a) : "l"(p));
    return a;
}
__device__ __forceinline__ void ldsm4(uint32_t addr, uint32_t r[4]) {
    asm volatile("ldmatrix.sync.aligned.m8n8.x4.shared.b16 {%0,%1,%2,%3}, [%4];"
                 : "=r"(r[0]), "=r"(r[1]), "=r"(r[2]), "=r"(r[3]) : "r"(addr));
}
__device__ __forceinline__ void mma16816(float d[4], const uint32_t a[4],
                                         const uint32_t b0, const uint32_t b1) {
    asm volatile(
        "mma.sync.aligned.m16n8k16.row.col.f32.bf16.bf16.f32 "
        "{%0,%1,%2,%3},{%4,%5,%6,%7},{%8,%9},{%0,%1,%2,%3};"
        : "+f"(d[0]), "+f"(d[1]), "+f"(d[2]), "+f"(d[3])
        : "r"(a[0]), "r"(a[1]), "r"(a[2]), "r"(a[3]), "r"(b0), "r"(b1));
}
__device__ __forceinline__ void cp16(uint32_t saddr, const void* gaddr) {
    asm volatile("cp.async.cg.shared.global [%0], [%1], 16;"
                 :: "r"(saddr), "l"(gaddr));
}
#define CP_COMMIT() asm volatile("cp.async.commit_group;" ::: "memory")
#define CP_WAIT(n)  asm volatile("cp.async.wait_group %0;" :: "n"(n) : "memory")

__device__ __forceinline__ uint32_t pack2(__nv_bfloat16 a, __nv_bfloat16 b) {
    return ((uint32_t)__bfloat16_as_ushort(b) << 16) | __bfloat16_as_ushort(a);
}
__device__ __forceinline__ void split1(float v, __nv_bfloat16& h, __nv_bfloat16& l) {
    h = __float2bfloat16(v);
    l = __float2bfloat16(v - __bfloat162float(h));
}

// Fast e^x on the FMA pipe (x <= 0 after max-subtraction). |err| ~ 1e-7 rel.
__device__ __forceinline__ float fexp(float x) {
    float y = fmaxf(x * 1.4426950408889634f, -120.f);   // log2(e), clamp
    float t = y + 12582912.f;                           // 1.5 * 2^23
    int   ki = __float_as_int(t) - 0x4b400000;          // round(y)
    float f = y - (t - 12582912.f);                     // [-0.5, 0.5]
    float p = 1.3333558146e-3f;
    p = fmaf(p, f, 9.6181291071e-3f);
    p = fmaf(p, f, 5.5504108664e-2f);
    p = fmaf(p, f, 2.4022650695e-1f);
    p = fmaf(p, f, 6.9314718056e-1f);
    p = fmaf(p, f, 1.0f);
    return __int_as_float(__float_as_int(p) + (ki << 23));
}

// ---------------------------------------------------------------------------
// Split pass: fp32 [n] -> bf16 hi[n] + lo[n]
// ---------------------------------------------------------------------------
__global__ void split_f32(const float* __restrict__ src,
                          __nv_bfloat16* __restrict__ hi,
                          __nv_bfloat16* __restrict__ lo, long long n)
{
    long long i = ((long long)blockIdx.x * blockDim.x + threadIdx.x) * 8;
    if (i >= n) return;
    float4 v0 = *(const float4*)(src + i);
    float4 v1 = *(const float4*)(src + i + 4);
    float f[8] = {v0.x, v0.y, v0.z, v0.w, v1.x, v1.y, v1.z, v1.w};
    uint32_t H[4], L[4];
#pragma unroll
    for (int j = 0; j < 4; j++) {
        __nv_bfloat16 h0, h1, l0, l1;
        split1(f[2 * j], h0, l0);
        split1(f[2 * j + 1], h1, l1);
        H[j] = pack2(h0, h1);
        L[j] = pack2(l0, l1);
    }
    *(uint4*)(hi + i) = make_uint4(H[0], H[1], H[2], H[3]);
    *(uint4*)(lo + i) = make_uint4(L[0], L[1], L[2], L[3]);
}

// ---------------------------------------------------------------------------
// HMMA GEMM (NT), 2-stage pipelined, BK=32.
// smem per stage: 4 tiles (Ah,Al,Bh,Bl) of 128 rows x 64B.
// Swizzle: 16B chunk index ^= (row>>1)&3  (conflict-free ldmatrix phases).
// 8 warps = 4(M) x 2(N); warp tile 32x64; 2 CTAs/SM.
// ---------------------------------------------------------------------------
#define TBH     8192                 // bytes per tile (128 x 32 bf16)
#define STAGE_B (4 * TBH)            // 32 KB per stage

__global__ __launch_bounds__(256, 2)
void gemm_split(const __nv_bfloat16* __restrict__ Ah,
                const __nv_bfloat16* __restrict__ Al,
                const __nv_bfloat16* __restrict__ Bh,
                const __nv_bfloat16* __restrict__ Bl,
                const float* __restrict__ bias, float* __restrict__ C,
                int M, int N, int K)
{
    extern __shared__ char sm[];
    const uint32_t sb = smem_u32(sm);

    const int tid  = threadIdx.x;
    const int lane = tid & 31;
    const int wid  = tid >> 5;
    const int wm   = wid & 3;
    const int wn   = wid >> 2;
    const long long m0 = (long long)blockIdx.y * 128;
    const int n0 = blockIdx.x * 128;

    float acc[2][8][4];
#pragma unroll
    for (int i = 0; i < 2; i++)
#pragma unroll
        for (int j = 0; j < 8; j++)
#pragma unroll
            for (int l = 0; l < 4; l++) acc[i][j][l] = 0.f;

    const int arow0 = wm * 32 + (lane & 7) + ((lane >> 3) & 1) * 8;
    const int ac    = lane >> 4;
    const int brow0 = wn * 64 + (lane & 7) + (lane >> 4) * 8;
    const int bc    = (lane >> 3) & 1;

    // fill: 512 16B-slots per tile; thread t handles slots {2t, 2t+1}
    const int s0row = (tid * 2) >> 2;
    const int s0c   = (tid * 2) & 3;
    const int s1row = (tid * 2 + 1) >> 2;
    const int s1c   = (tid * 2 + 1) & 3;

    const int NCH = K >> 5;          // 32-wide chunks

    auto fill = [&](int ch, int st) {
        const uint32_t so = sb + st * STAGE_B;
#pragma unroll
        for (int i = 0; i < 2; i++) {
            int row = i ? s1row : s0row;
            int c   = i ? s1c   : s0c;
            uint32_t off = (uint32_t)(row * 64 + ((c ^ ((row >> 1) & 3)) << 4));
            long long ga = (m0 + row) * K + ch * 32 + c * 8;
            long long gb = (long long)(n0 + row) * K + ch * 32 + c * 8;
            cp16(so + off,           Ah + ga);
            cp16(so + TBH + off,     Al + ga);
            cp16(so + 2 * TBH + off, Bh + gb);
            cp16(so + 3 * TBH + off, Bl + gb);
        }
        CP_COMMIT();
    };

    fill(0, 0);

    for (int ch = 0; ch < NCH; ch++) {
        const int st = ch & 1;
        if (ch + 1 < NCH) {
            fill(ch + 1, (ch + 1) & 1);
            CP_WAIT(1);              // stage `st` (chunk ch) landed
        } else {
            CP_WAIT(0);
        }
        __syncthreads();

        const uint32_t so = sb + st * STAGE_B;
#pragma unroll
        for (int kk = 0; kk < 2; kk++) {
            uint32_t ah[2][4], al[2][4];
#pragma unroll
            for (int mt = 0; mt < 2; mt++) {
                int r = arow0 + mt * 16;
                uint32_t off = (uint32_t)(r * 64 + (((2 * kk + ac) ^ ((r >> 1) & 3)) << 4));
                ldsm4(so + off, ah[mt]);
                ldsm4(so + TBH + off, al[mt]);
            }
#pragma unroll
            for (int nt = 0; nt < 4; nt++) {
                int r = brow0 + nt * 16;
                uint32_t off = (uint32_t)(r * 64 + (((2 * kk + bc) ^ ((r >> 1) & 3)) << 4));
                uint32_t bh[4], bl[4];
                ldsm4(so + 2 * TBH + off, bh);
                ldsm4(so + 3 * TBH + off, bl);
#pragma unroll
                for (int mt = 0; mt < 2; mt++) {
                    mma16816(acc[mt][nt * 2],     ah[mt], bh[0], bh[1]);
                    mma16816(acc[mt][nt * 2 + 1], ah[mt], bh[2], bh[3]);
                    mma16816(acc[mt][nt * 2],     ah[mt], bl[0], bl[1]);
                    mma16816(acc[mt][nt * 2 + 1], ah[mt], bl[2], bl[3]);
                    mma16816(acc[mt][nt * 2],     al[mt], bh[0], bh[1]);
                    mma16816(acc[mt][nt * 2 + 1], al[mt], bh[2], bh[3]);
                }
            }
        }
        __syncthreads();             // done reading stage before it refills
    }

    const int erow = lane >> 2;
    const int ecol = (lane & 3) * 2;
#pragma unroll
    for (int mt = 0; mt < 2; mt++) {
#pragma unroll
        for (int nt8 = 0; nt8 < 8; nt8++) {
            long long row = m0 + wm * 32 + mt * 16 + erow;
            int col = n0 + wn * 64 + nt8 * 8 + ecol;
            float b0 = bias ? bias[col]     : 0.f;
            float b1 = bias ? bias[col + 1] : 0.f;
            float2 r0 = make_float2(acc[mt][nt8][0] + b0, acc[mt][nt8][1] + b1);
            float2 r1 = make_float2(acc[mt][nt8][2] + b0, acc[mt][nt8][3] + b1);
            *(float2*)(C + row * N + col)       = r0;
            *(float2*)(C + (row + 8) * N + col) = r1;
        }
    }
}

// ---------------------------------------------------------------------------
// Windowed attention: one CTA per (window, head). fp32 math, FMA-pipe exp;
// epilogue emits bf16 hi/lo split for the projection GEMM.
// ---------------------------------------------------------------------------
__global__ __launch_bounds__(64)
void attn64(const float* __restrict__ qkv,
            __nv_bfloat16* __restrict__ oh, __nv_bfloat16* __restrict__ ol)
{
    extern __shared__ float smf[];
    float* qt  = smf;
    float* kt  = smf + 4160;
    float* vs  = smf + 8320;
    float* inv = smf + 12416;

    const int tid = threadIdx.x;
    const int h  = blockIdx.x;
    const int wb = blockIdx.y;

    const float* base = qkv + (long long)wb * WINW * QKV_DIM + h * HD;

    for (int idx = tid; idx < 1024; idx += 64) {
        int w = idx >> 4;
        int e = (idx & 15) << 2;
        const float* p = base + (long long)w * QKV_DIM + e;
        float4 q4 = *(const float4*)(p);
        float4 k4 = *(const float4*)(p + 512);
        float4 v4 = *(const float4*)(p + 1024);
        qt[(e + 0) * 65 + w] = q4.x; qt[(e + 1) * 65 + w] = q4.y;
        qt[(e + 2) * 65 + w] = q4.z; qt[(e + 3) * 65 + w] = q4.w;
        kt[(e + 0) * 65 + w] = k4.x; kt[(e + 1) * 65 + w] = k4.y;
        kt[(e + 2) * 65 + w] = k4.z; kt[(e + 3) * 65 + w] = k4.w;
        *(float4*)&vs[w * 64 + e] = v4;
    }
    __syncthreads();

    const int rr = (tid >> 3) << 3;
    const int cc = (tid & 7) << 3;

    float s[8][8];
#pragma unroll
    for (int i = 0; i < 8; i++)
#pragma unroll
        for (int j = 0; j < 8; j++) s[i][j] = 0.f;

#pragma unroll 4
    for (int e = 0; e < 64; e++) {
        float a[8], b[8];
#pragma unroll
        for (int i = 0; i < 8; i++) a[i] = qt[e * 65 + rr + i];
#pragma unroll
        for (int j = 0; j < 8; j++) b[j] = kt[e * 65 + cc + j];
#pragma unroll
        for (int i = 0; i < 8; i++)
#pragma unroll
            for (int j = 0; j < 8; j++)
                s[i][j] += a[i] * b[j];
    }
    __syncthreads();

    float* St = qt;
#pragma unroll
    for (int i = 0; i < 8; i++)
#pragma unroll
        for (int j = 0; j < 8; j++)
            St[(cc + j) * 64 + rr + i] = s[i][j] * 0.125f;
    __syncthreads();

    {
        int r = tid;
        float mx = -1e30f;
#pragma unroll 8
        for (int j = 0; j < 64; j++) mx = fmaxf(mx, St[j * 64 + r]);
        float sum = 0.f;
#pragma unroll 8
        for (int j = 0; j < 64; j++) {
            float p = fexp(St[j * 64 + r] - mx);
            St[j * 64 + r] = p;
            sum += p;
        }
        inv[r] = 1.0f / sum;
    }
    __syncthreads();

    float o[8][8];
#pragma unroll
    for (int i = 0; i < 8; i++)
#pragma unroll
        for (int j = 0; j < 8; j++) o[i][j] = 0.f;

#pragma unroll 4
    for (int j = 0; j < 64; j++) {
        float p[8], b[8];
#pragma unroll
        for (int i = 0; i < 8; i++) p[i] = St[j * 64 + rr + i];
        *(float4*)(b)     = *(const float4*)&vs[j * 64 + cc];
        *(float4*)(b + 4) = *(const float4*)&vs[j * 64 + cc + 4];
#pragma unroll
        for (int i = 0; i < 8; i++)
#pragma unroll
            for (int jj = 0; jj < 8; jj++)
                o[i][jj] += p[i] * b[jj];
    }

#pragma unroll
    for (int i = 0; i < 8; i++) {
        float sc = inv[rr + i];
        long long pos = ((long long)wb * WINW + rr + i) * C_DIM + h * HD + cc;
        uint32_t H[4], L[4];
#pragma unroll
        for (int j = 0; j < 4; j++) {
            __nv_bfloat16 h0, h1, l0, l1;
            split1(o[i][2 * j] * sc, h0, l0);
            split1(o[i][2 * j + 1] * sc, h1, l1);
            H[j] = pack2(h0, h1);
            L[j] = pack2(l0, l1);
        }
        *(uint4*)(oh + pos) = make_uint4(H[0], H[1], H[2], H[3]);
        *(uint4*)(ol + pos) = make_uint4(L[0], L[1], L[2], L[3]);
    }
}

// ---------------------------------------------------------------------------
extern "C" void kernel_launch(void* const* d_in, const int* in_sizes, int n_in,
                              void* d_out, int out_size)
{
    const float* x      = (const float*)d_in[0];
    const float* qkv_w  = (const float*)d_in[1];
    const float* proj_w = (const float*)d_in[2];
    const float* proj_b = (const float*)d_in[3];
    float* out = (float*)d_out;

    float *qkv_buf = nullptr;
    __nv_bfloat16 *xh, *xl, *ath, *atl, *wqh, *wql, *wph, *wpl;
    cudaGetSymbolAddress((void**)&qkv_buf, g_qkv);
    cudaGetSymbolAddress((void**)&xh,  g_xh);
    cudaGetSymbolAddress((void**)&xl,  g_xl);
    cudaGetSymbolAddress((void**)&ath, g_ath);
    cudaGetSymbolAddress((void**)&atl, g_atl);
    cudaGetSymbolAddress((void**)&wqh, g_wqh);
    cudaGetSymbolAddress((void**)&wql, g_wql);
    cudaGetSymbolAddress((void**)&wph, g_wph);
    cudaGetSymbolAddress((void**)&wpl, g_wpl);

    const int gemm_smem = 2 * STAGE_B;    // 64 KB
    cudaFuncSetAttribute(gemm_split, cudaFuncAttributeMaxDynamicSharedMemorySize,
                         gemm_smem);
    cudaFuncSetAttribute(attn64, cudaFuncAttributeMaxDynamicSharedMemorySize,
                         12480 * (int)sizeof(float));

    // 0) split inputs to bf16 hi/lo
    {
        long long nx = (long long)M_ROWS * C_DIM;
        split_f32<<<(unsigned)((nx / 8 + 255) / 256), 256>>>(x, xh, xl, nx);
        long long nq = (long long)QKV_DIM * C_DIM;
        split_f32<<<(unsigned)((nq / 8 + 255) / 256), 256>>>(qkv_w, wqh, wql, nq);
        long long np = (long long)C_DIM * C_DIM;
        split_f32<<<(unsigned)((np / 8 + 255) / 256), 256>>>(proj_w, wph, wpl, np);
    }

    // 1) QKV projection
    gemm_split<<<dim3(QKV_DIM / 128, M_ROWS / 128), 256, gemm_smem>>>(
        xh, xl, wqh, wql, nullptr, qkv_buf, M_ROWS, QKV_DIM, C_DIM);

    // 2) Windowed attention (emits bf16 hi/lo)
    attn64<<<dim3(NH, NWIN), 64, 12480 * sizeof(float)>>>(qkv_buf, ath, atl);

    // 3) Output projection (+bias)
    gemm_split<<<dim3(C_DIM / 128, M_ROWS / 128), 256, gemm_smem>>>(
        ath, atl, wph, wpl, proj_b, out, M_ROWS, C_DIM, C_DIM);
}

// round 7
// speedup vs baseline: 1.1709x; 1.1709x over previous
#include <cuda_runtime.h>
#include <cuda_bf16.h>
#include <cstdint>

// ---------------------------------------------------------------------------
// x[65536,512] -> qkv = x @ qkv_w^T -> windowed attn (1024x8, 64x64x64)
//   -> out = att @ proj_w^T + b
// GEMMs: HMMA bf16 3-term hi/lo split, BK=64 single-buffer + 2 CTA/SM overlap
// (round-4 proven config). Attention: fp32 with FMA-pipe polynomial exp.
// ---------------------------------------------------------------------------

#define M_ROWS   65536
#define C_DIM    512
#define QKV_DIM  1536
#define NH       8
#define HD       64
#define WINW     64
#define NWIN     1024

__device__ float         g_qkv[(long long)M_ROWS * QKV_DIM];
__device__ __nv_bfloat16 g_xh [(long long)M_ROWS * C_DIM];
__device__ __nv_bfloat16 g_xl [(long long)M_ROWS * C_DIM];
__device__ __nv_bfloat16 g_ath[(long long)M_ROWS * C_DIM];
__device__ __nv_bfloat16 g_atl[(long long)M_ROWS * C_DIM];
__device__ __nv_bfloat16 g_wqh[QKV_DIM * C_DIM];
__device__ __nv_bfloat16 g_wql[QKV_DIM * C_DIM];
__device__ __nv_bfloat16 g_wph[C_DIM * C_DIM];
__device__ __nv_bfloat16 g_wpl[C_DIM * C_DIM];

// ------------------------------ helpers ------------------------------------
__device__ __forceinline__ uint32_t smem_u32(const void* p) {
    uint32_t a;
    asm("{ .reg .u64 t; cvta.to.shared.u64 t, %1; cvt.u32.u64 %0, t; }"
        : "=r"(a) : "l"(p));
    return a;
}
__device__ __forceinline__ void ldsm4(uint32_t addr, uint32_t r[4]) {
    asm volatile("ldmatrix.sync.aligned.m8n8.x4.shared.b16 {%0,%1,%2,%3}, [%4];"
                 : "=r"(r[0]), "=r"(r[1]), "=r"(r[2]), "=r"(r[3]) : "r"(addr));
}
__device__ __forceinline__ void mma16816(float d[4], const uint32_t a[4],
                                         const uint32_t b0, const uint32_t b1) {
    asm volatile(
        "mma.sync.aligned.m16n8k16.row.col.f32.bf16.bf16.f32 "
        "{%0,%1,%2,%3},{%4,%5,%6,%7},{%8,%9},{%0,%1,%2,%3};"
        : "+f"(d[0]), "+f"(d[1]), "+f"(d[2]), "+f"(d[3])
        : "r"(a[0]), "r"(a[1]), "r"(a[2]), "r"(a[3]), "r"(b0), "r"(b1));
}
__device__ __forceinline__ void cp16(uint32_t saddr, const void* gaddr) {
    asm volatile("cp.async.cg.shared.global [%0], [%1], 16;"
                 :: "r"(saddr), "l"(gaddr));
}
#define CP_COMMIT() asm volatile("cp.async.commit_group;" ::: "memory")
#define CP_WAIT0()  asm volatile("cp.async.wait_group 0;" ::: "memory")

__device__ __forceinline__ uint32_t pack2(__nv_bfloat16 a, __nv_bfloat16 b) {
    return ((uint32_t)__bfloat16_as_ushort(b) << 16) | __bfloat16_as_ushort(a);
}
__device__ __forceinline__ void split1(float v, __nv_bfloat16& h, __nv_bfloat16& l) {
    h = __float2bfloat16(v);
    l = __float2bfloat16(v - __bfloat162float(h));
}

// Fast e^x on the FMA pipe (x <= 0 after max-subtraction). |err| ~ 1e-7 rel.
__device__ __forceinline__ float fexp(float x) {
    float y = fmaxf(x * 1.4426950408889634f, -120.f);   // log2(e), clamp
    float t = y + 12582912.f;                           // 1.5 * 2^23
    int   ki = __float_as_int(t) - 0x4b400000;          // round(y)
    float f = y - (t - 12582912.f);                     // [-0.5, 0.5]
    float p = 1.3333558146e-3f;
    p = fmaf(p, f, 9.6181291071e-3f);
    p = fmaf(p, f, 5.5504108664e-2f);
    p = fmaf(p, f, 2.4022650695e-1f);
    p = fmaf(p, f, 6.9314718056e-1f);
    p = fmaf(p, f, 1.0f);
    return __int_as_float(__float_as_int(p) + (ki << 23));
}

// ---------------------------------------------------------------------------
// Split pass: fp32 [n] -> bf16 hi[n] + lo[n]
// ---------------------------------------------------------------------------
__global__ void split_f32(const float* __restrict__ src,
                          __nv_bfloat16* __restrict__ hi,
                          __nv_bfloat16* __restrict__ lo, long long n)
{
    long long i = ((long long)blockIdx.x * blockDim.x + threadIdx.x) * 8;
    if (i >= n) return;
    float4 v0 = *(const float4*)(src + i);
    float4 v1 = *(const float4*)(src + i + 4);
    float f[8] = {v0.x, v0.y, v0.z, v0.w, v1.x, v1.y, v1.z, v1.w};
    uint32_t H[4], L[4];
#pragma unroll
    for (int j = 0; j < 4; j++) {
        __nv_bfloat16 h0, h1, l0, l1;
        split1(f[2 * j], h0, l0);
        split1(f[2 * j + 1], h1, l1);
        H[j] = pack2(h0, h1);
        L[j] = pack2(l0, l1);
    }
    *(uint4*)(hi + i) = make_uint4(H[0], H[1], H[2], H[3]);
    *(uint4*)(lo + i) = make_uint4(L[0], L[1], L[2], L[3]);
}

// ---------------------------------------------------------------------------
// HMMA GEMM (NT) on preconverted bf16 hi/lo: C = A*B^T (+bias), fp32 out.
// CTA 128x128, BK=64. smem: 4 tiles (Ah,Al,Bh,Bl) of 128 rows x 128B, xor
// swizzle per 16B chunk. Fill via cp.async.cg. 8 warps = 4(M) x 2(N).
// (round-4 configuration: 666us QKV, tensor=77%)
// ---------------------------------------------------------------------------
#define TB 16384

__global__ __launch_bounds__(256, 2)
void gemm_split(const __nv_bfloat16* __restrict__ Ah,
                const __nv_bfloat16* __restrict__ Al,
                const __nv_bfloat16* __restrict__ Bh,
                const __nv_bfloat16* __restrict__ Bl,
                const float* __restrict__ bias, float* __restrict__ C,
                int M, int N, int K)
{
    extern __shared__ char sm[];
    const uint32_t sb = smem_u32(sm);

    const int tid  = threadIdx.x;
    const int lane = tid & 31;
    const int wid  = tid >> 5;
    const int wm   = wid & 3;
    const int wn   = wid >> 2;
    const long long m0 = (long long)blockIdx.y * 128;
    const int n0 = blockIdx.x * 128;

    float acc[2][8][4];
#pragma unroll
    for (int i = 0; i < 2; i++)
#pragma unroll
        for (int j = 0; j < 8; j++)
#pragma unroll
            for (int l = 0; l < 4; l++) acc[i][j][l] = 0.f;

    const int arow0 = wm * 32 + (lane & 7) + ((lane >> 3) & 1) * 8;
    const int ac    = lane >> 4;
    const int brow0 = wn * 64 + (lane & 7) + (lane >> 4) * 8;
    const int bc    = (lane >> 3) & 1;

    const int frow = tid >> 3;
    const int fc   = tid & 7;

    const int NCH = K >> 6;
    for (int ch = 0; ch < NCH; ch++) {
        __syncthreads();
#pragma unroll
        for (int i = 0; i < 4; i++) {
            int row = frow + i * 32;
            uint32_t off = (uint32_t)(row * 128 + ((fc ^ (row & 7)) << 4));
            long long ga = (m0 + row) * K + ch * 64 + fc * 8;
            long long gb = (long long)(n0 + row) * K + ch * 64 + fc * 8;
            cp16(sb + off,          Ah + ga);
            cp16(sb + TB + off,     Al + ga);
            cp16(sb + 2 * TB + off, Bh + gb);
            cp16(sb + 3 * TB + off, Bl + gb);
        }
        CP_COMMIT();
        CP_WAIT0();
        __syncthreads();

#pragma unroll
        for (int kk = 0; kk < 4; kk++) {
            uint32_t ah[2][4], al[2][4];
#pragma unroll
            for (int mt = 0; mt < 2; mt++) {
                int r = arow0 + mt * 16;
                uint32_t off = (uint32_t)(r * 128 + (((2 * kk + ac) ^ (r & 7)) << 4));
                ldsm4(sb + off, ah[mt]);
                ldsm4(sb + TB + off, al[mt]);
            }
#pragma unroll
            for (int nt = 0; nt < 4; nt++) {
                int r = brow0 + nt * 16;
                uint32_t off = (uint32_t)(r * 128 + (((2 * kk + bc) ^ (r & 7)) << 4));
                uint32_t bh[4], bl[4];
                ldsm4(sb + 2 * TB + off, bh);
                ldsm4(sb + 3 * TB + off, bl);
#pragma unroll
                for (int mt = 0; mt < 2; mt++) {
                    mma16816(acc[mt][nt * 2],     ah[mt], bh[0], bh[1]);
                    mma16816(acc[mt][nt * 2 + 1], ah[mt], bh[2], bh[3]);
                    mma16816(acc[mt][nt * 2],     ah[mt], bl[0], bl[1]);
                    mma16816(acc[mt][nt * 2 + 1], ah[mt], bl[2], bl[3]);
                    mma16816(acc[mt][nt * 2],     al[mt], bh[0], bh[1]);
                    mma16816(acc[mt][nt * 2 + 1], al[mt], bh[2], bh[3]);
                }
            }
        }
    }

    const int erow = lane >> 2;
    const int ecol = (lane & 3) * 2;
#pragma unroll
    for (int mt = 0; mt < 2; mt++) {
#pragma unroll
        for (int nt8 = 0; nt8 < 8; nt8++) {
            long long row = m0 + wm * 32 + mt * 16 + erow;
            int col = n0 + wn * 64 + nt8 * 8 + ecol;
            float b0 = bias ? bias[col]     : 0.f;
            float b1 = bias ? bias[col + 1] : 0.f;
            float2 r0 = make_float2(acc[mt][nt8][0] + b0, acc[mt][nt8][1] + b1);
            float2 r1 = make_float2(acc[mt][nt8][2] + b0, acc[mt][nt8][3] + b1);
            *(float2*)(C + row * N + col)       = r0;
            *(float2*)(C + (row + 8) * N + col) = r1;
        }
    }
}

// ---------------------------------------------------------------------------
// Windowed attention: one CTA per (window, head). fp32 math, FMA-pipe exp;
// epilogue emits bf16 hi/lo split for the projection GEMM.
// ---------------------------------------------------------------------------
__global__ __launch_bounds__(64)
void attn64(const float* __restrict__ qkv,
            __nv_bfloat16* __restrict__ oh, __nv_bfloat16* __restrict__ ol)
{
    extern __shared__ float smf[];
    float* qt  = smf;
    float* kt  = smf + 4160;
    float* vs  = smf + 8320;
    float* inv = smf + 12416;

    const int tid = threadIdx.x;
    const int h  = blockIdx.x;
    const int wb = blockIdx.y;

    const float* base = qkv + (long long)wb * WINW * QKV_DIM + h * HD;

    for (int idx = tid; idx < 1024; idx += 64) {
        int w = idx >> 4;
        int e = (idx & 15) << 2;
        const float* p = base + (long long)w * QKV_DIM + e;
        float4 q4 = *(const float4*)(p);
        float4 k4 = *(const float4*)(p + 512);
        float4 v4 = *(const float4*)(p + 1024);
        qt[(e + 0) * 65 + w] = q4.x; qt[(e + 1) * 65 + w] = q4.y;
        qt[(e + 2) * 65 + w] = q4.z; qt[(e + 3) * 65 + w] = q4.w;
        kt[(e + 0) * 65 + w] = k4.x; kt[(e + 1) * 65 + w] = k4.y;
        kt[(e + 2) * 65 + w] = k4.z; kt[(e + 3) * 65 + w] = k4.w;
        *(float4*)&vs[w * 64 + e] = v4;
    }
    __syncthreads();

    const int rr = (tid >> 3) << 3;
    const int cc = (tid & 7) << 3;

    float s[8][8];
#pragma unroll
    for (int i = 0; i < 8; i++)
#pragma unroll
        for (int j = 0; j < 8; j++) s[i][j] = 0.f;

#pragma unroll 4
    for (int e = 0; e < 64; e++) {
        float a[8], b[8];
#pragma unroll
        for (int i = 0; i < 8; i++) a[i] = qt[e * 65 + rr + i];
#pragma unroll
        for (int j = 0; j < 8; j++) b[j] = kt[e * 65 + cc + j];
#pragma unroll
        for (int i = 0; i < 8; i++)
#pragma unroll
            for (int j = 0; j < 8; j++)
                s[i][j] += a[i] * b[j];
    }
    __syncthreads();

    float* St = qt;
#pragma unroll
    for (int i = 0; i < 8; i++)
#pragma unroll
        for (int j = 0; j < 8; j++)
            St[(cc + j) * 64 + rr + i] = s[i][j] * 0.125f;
    __syncthreads();

    {
        int r = tid;
        float mx = -1e30f;
#pragma unroll 8
        for (int j = 0; j < 64; j++) mx = fmaxf(mx, St[j * 64 + r]);
        float sum = 0.f;
#pragma unroll 8
        for (int j = 0; j < 64; j++) {
            float p = fexp(St[j * 64 + r] - mx);
            St[j * 64 + r] = p;
            sum += p;
        }
        inv[r] = 1.0f / sum;
    }
    __syncthreads();

    float o[8][8];
#pragma unroll
    for (int i = 0; i < 8; i++)
#pragma unroll
        for (int j = 0; j < 8; j++) o[i][j] = 0.f;

#pragma unroll 4
    for (int j = 0; j < 64; j++) {
        float p[8], b[8];
#pragma unroll
        for (int i = 0; i < 8; i++) p[i] = St[j * 64 + rr + i];
        *(float4*)(b)     = *(const float4*)&vs[j * 64 + cc];
        *(float4*)(b + 4) = *(const float4*)&vs[j * 64 + cc + 4];
#pragma unroll
        for (int i = 0; i < 8; i++)
#pragma unroll
            for (int jj = 0; jj < 8; jj++)
                o[i][jj] += p[i] * b[jj];
    }

#pragma unroll
    for (int i = 0; i < 8; i++) {
        float sc = inv[rr + i];
        long long pos = ((long long)wb * WINW + rr + i) * C_DIM + h * HD + cc;
        uint32_t H[4], L[4];
#pragma unroll
        for (int j = 0; j < 4; j++) {
            __nv_bfloat16 h0, h1, l0, l1;
            split1(o[i][2 * j] * sc, h0, l0);
            split1(o[i][2 * j + 1] * sc, h1, l1);
            H[j] = pack2(h0, h1);
            L[j] = pack2(l0, l1);
        }
        *(uint4*)(oh + pos) = make_uint4(H[0], H[1], H[2], H[3]);
        *(uint4*)(ol + pos) = make_uint4(L[0], L[1], L[2], L[3]);
    }
}

// ---------------------------------------------------------------------------
extern "C" void kernel_launch(void* const* d_in, const int* in_sizes, int n_in,
                              void* d_out, int out_size)
{
    const float* x      = (const float*)d_in[0];
    const float* qkv_w  = (const float*)d_in[1];
    const float* proj_w = (const float*)d_in[2];
    const float* proj_b = (const float*)d_in[3];
    float* out = (float*)d_out;

    float *qkv_buf = nullptr;
    __nv_bfloat16 *xh, *xl, *ath, *atl, *wqh, *wql, *wph, *wpl;
    cudaGetSymbolAddress((void**)&qkv_buf, g_qkv);
    cudaGetSymbolAddress((void**)&xh,  g_xh);
    cudaGetSymbolAddress((void**)&xl,  g_xl);
    cudaGetSymbolAddress((void**)&ath, g_ath);
    cudaGetSymbolAddress((void**)&atl, g_atl);
    cudaGetSymbolAddress((void**)&wqh, g_wqh);
    cudaGetSymbolAddress((void**)&wql, g_wql);
    cudaGetSymbolAddress((void**)&wph, g_wph);
    cudaGetSymbolAddress((void**)&wpl, g_wpl);

    const int gemm_smem = 4 * TB;     // 64 KB
    cudaFuncSetAttribute(gemm_split, cudaFuncAttributeMaxDynamicSharedMemorySize,
                         gemm_smem);
    cudaFuncSetAttribute(attn64, cudaFuncAttributeMaxDynamicSharedMemorySize,
                         12480 * (int)sizeof(float));

    // 0) split inputs to bf16 hi/lo
    {
        long long nx = (long long)M_ROWS * C_DIM;
        split_f32<<<(unsigned)((nx / 8 + 255) / 256), 256>>>(x, xh, xl, nx);
        long long nq = (long long)QKV_DIM * C_DIM;
        split_f32<<<(unsigned)((nq / 8 + 255) / 256), 256>>>(qkv_w, wqh, wql, nq);
        long long np = (long long)C_DIM * C_DIM;
        split_f32<<<(unsigned)((np / 8 + 255) / 256), 256>>>(proj_w, wph, wpl, np);
    }

    // 1) QKV projection
    gemm_split<<<dim3(QKV_DIM / 128, M_ROWS / 128), 256, gemm_smem>>>(
        xh, xl, wqh, wql, nullptr, qkv_buf, M_ROWS, QKV_DIM, C_DIM);

    // 2) Windowed attention (emits bf16 hi/lo)
    attn64<<<dim3(NH, NWIN), 64, 12480 * sizeof(float)>>>(qkv_buf, ath, atl);

    // 3) Output projection (+bias)
    gemm_split<<<dim3(C_DIM / 128, M_ROWS / 128), 256, gemm_smem>>>(
        ath, atl, wph, wpl, proj_b, out, M_ROWS, C_DIM, C_DIM);
}

// round 12
// speedup vs baseline: 1.4022x; 1.1975x over previous
#include <cuda_runtime.h>
#include <cuda_bf16.h>
#include <cstdint>

// ---------------------------------------------------------------------------
// x[65536,512] -> qkv = x @ qkv_w^T -> windowed attn (1024x8, 64x64x64)
//   -> out = att @ proj_w^T + b
// GEMMs: HMMA bf16 3-term hi/lo split, BK=64 single-buffer + 2 CTA/SM overlap
// (proven config). Attention: HMMA-tensorized flash-style, softmax in regs.
// ---------------------------------------------------------------------------

#define M_ROWS   65536
#define C_DIM    512
#define QKV_DIM  1536
#define NH       8
#define HD       64
#define WINW     64
#define NWIN     1024

__device__ float         g_qkv[(long long)M_ROWS * QKV_DIM];
__device__ __nv_bfloat16 g_xh [(long long)M_ROWS * C_DIM];
__device__ __nv_bfloat16 g_xl [(long long)M_ROWS * C_DIM];
__device__ __nv_bfloat16 g_ath[(long long)M_ROWS * C_DIM];
__device__ __nv_bfloat16 g_atl[(long long)M_ROWS * C_DIM];
__device__ __nv_bfloat16 g_wqh[QKV_DIM * C_DIM];
__device__ __nv_bfloat16 g_wql[QKV_DIM * C_DIM];
__device__ __nv_bfloat16 g_wph[C_DIM * C_DIM];
__device__ __nv_bfloat16 g_wpl[C_DIM * C_DIM];

// ------------------------------ helpers ------------------------------------
__device__ __forceinline__ uint32_t smem_u32(const void* p) {
    uint32_t a;
    asm("{ .reg .u64 t; cvta.to.shared.u64 t, %1; cvt.u32.u64 %0, t; }"
        : "=r"(a) : "l"(p));
    return a;
}
__device__ __forceinline__ void ldsm4(uint32_t addr, uint32_t r[4]) {
    asm volatile("ldmatrix.sync.aligned.m8n8.x4.shared.b16 {%0,%1,%2,%3}, [%4];"
                 : "=r"(r[0]), "=r"(r[1]), "=r"(r[2]), "=r"(r[3]) : "r"(addr));
}
__device__ __forceinline__ void mma16816(float d[4], const uint32_t a[4],
                                         const uint32_t b0, const uint32_t b1) {
    asm volatile(
        "mma.sync.aligned.m16n8k16.row.col.f32.bf16.bf16.f32 "
        "{%0,%1,%2,%3},{%4,%5,%6,%7},{%8,%9},{%0,%1,%2,%3};"
        : "+f"(d[0]), "+f"(d[1]), "+f"(d[2]), "+f"(d[3])
        : "r"(a[0]), "r"(a[1]), "r"(a[2]), "r"(a[3]), "r"(b0), "r"(b1));
}
__device__ __forceinline__ void cp16(uint32_t saddr, const void* gaddr) {
    asm volatile("cp.async.cg.shared.global [%0], [%1], 16;"
                 :: "r"(saddr), "l"(gaddr));
}
#define CP_COMMIT() asm volatile("cp.async.commit_group;" ::: "memory")
#define CP_WAIT0()  asm volatile("cp.async.wait_group 0;" ::: "memory")

__device__ __forceinline__ uint32_t pack2(__nv_bfloat16 a, __nv_bfloat16 b) {
    return ((uint32_t)__bfloat16_as_ushort(b) << 16) | __bfloat16_as_ushort(a);
}
__device__ __forceinline__ void split1(float v, __nv_bfloat16& h, __nv_bfloat16& l) {
    h = __float2bfloat16(v);
    l = __float2bfloat16(v - __bfloat162float(h));
}
// pack a float pair into bf16-hi and bf16-lo 32-bit fragments
__device__ __forceinline__ void split_pack(float x, float y,
                                           uint32_t& hh, uint32_t& ll) {
    __nv_bfloat16 h0, l0, h1, l1;
    split1(x, h0, l0);
    split1(y, h1, l1);
    hh = pack2(h0, h1);
    ll = pack2(l0, l1);
}

// Fast e^x on the FMA pipe (x <= 0). |err| ~ 1e-7 rel.
__device__ __forceinline__ float fexp(float x) {
    float y = fmaxf(x * 1.4426950408889634f, -120.f);
    float t = y + 12582912.f;
    int   ki = __float_as_int(t) - 0x4b400000;
    float f = y - (t - 12582912.f);
    float p = 1.3333558146e-3f;
    p = fmaf(p, f, 9.6181291071e-3f);
    p = fmaf(p, f, 5.5504108664e-2f);
    p = fmaf(p, f, 2.4022650695e-1f);
    p = fmaf(p, f, 6.9314718056e-1f);
    p = fmaf(p, f, 1.0f);
    return __int_as_float(__float_as_int(p) + (ki << 23));
}

// ---------------------------------------------------------------------------
// Split pass: fp32 [n] -> bf16 hi[n] + lo[n]
// ---------------------------------------------------------------------------
__global__ void split_f32(const float* __restrict__ src,
                          __nv_bfloat16* __restrict__ hi,
                          __nv_bfloat16* __restrict__ lo, long long n)
{
    long long i = ((long long)blockIdx.x * blockDim.x + threadIdx.x) * 8;
    if (i >= n) return;
    float4 v0 = *(const float4*)(src + i);
    float4 v1 = *(const float4*)(src + i + 4);
    float f[8] = {v0.x, v0.y, v0.z, v0.w, v1.x, v1.y, v1.z, v1.w};
    uint32_t H[4], L[4];
#pragma unroll
    for (int j = 0; j < 4; j++)
        split_pack(f[2 * j], f[2 * j + 1], H[j], L[j]);
    *(uint4*)(hi + i) = make_uint4(H[0], H[1], H[2], H[3]);
    *(uint4*)(lo + i) = make_uint4(L[0], L[1], L[2], L[3]);
}

// ---------------------------------------------------------------------------
// HMMA GEMM (NT) on preconverted bf16 hi/lo — round-4 proven config.
// ---------------------------------------------------------------------------
#define TB 16384

__global__ __launch_bounds__(256, 2)
void gemm_split(const __nv_bfloat16* __restrict__ Ah,
                const __nv_bfloat16* __restrict__ Al,
                const __nv_bfloat16* __restrict__ Bh,
                const __nv_bfloat16* __restrict__ Bl,
                const float* __restrict__ bias, float* __restrict__ C,
                int M, int N, int K)
{
    extern __shared__ char sm[];
    const uint32_t sb = smem_u32(sm);

    const int tid  = threadIdx.x;
    const int lane = tid & 31;
    const int wid  = tid >> 5;
    const int wm   = wid & 3;
    const int wn   = wid >> 2;
    const long long m0 = (long long)blockIdx.y * 128;
    const int n0 = blockIdx.x * 128;

    float acc[2][8][4];
#pragma unroll
    for (int i = 0; i < 2; i++)
#pragma unroll
        for (int j = 0; j < 8; j++)
#pragma unroll
            for (int l = 0; l < 4; l++) acc[i][j][l] = 0.f;

    const int arow0 = wm * 32 + (lane & 7) + ((lane >> 3) & 1) * 8;
    const int ac    = lane >> 4;
    const int brow0 = wn * 64 + (lane & 7) + (lane >> 4) * 8;
    const int bc    = (lane >> 3) & 1;

    const int frow = tid >> 3;
    const int fc   = tid & 7;

    const int NCH = K >> 6;
    for (int ch = 0; ch < NCH; ch++) {
        __syncthreads();
#pragma unroll
        for (int i = 0; i < 4; i++) {
            int row = frow + i * 32;
            uint32_t off = (uint32_t)(row * 128 + ((fc ^ (row & 7)) << 4));
            long long ga = (m0 + row) * K + ch * 64 + fc * 8;
            long long gb = (long long)(n0 + row) * K + ch * 64 + fc * 8;
            cp16(sb + off,          Ah + ga);
            cp16(sb + TB + off,     Al + ga);
            cp16(sb + 2 * TB + off, Bh + gb);
            cp16(sb + 3 * TB + off, Bl + gb);
        }
        CP_COMMIT();
        CP_WAIT0();
        __syncthreads();

#pragma unroll
        for (int kk = 0; kk < 4; kk++) {
            uint32_t ah[2][4], al[2][4];
#pragma unroll
            for (int mt = 0; mt < 2; mt++) {
                int r = arow0 + mt * 16;
                uint32_t off = (uint32_t)(r * 128 + (((2 * kk + ac) ^ (r & 7)) << 4));
                ldsm4(sb + off, ah[mt]);
                ldsm4(sb + TB + off, al[mt]);
            }
#pragma unroll
            for (int nt = 0; nt < 4; nt++) {
                int r = brow0 + nt * 16;
                uint32_t off = (uint32_t)(r * 128 + (((2 * kk + bc) ^ (r & 7)) << 4));
                uint32_t bh[4], bl[4];
                ldsm4(sb + 2 * TB + off, bh);
                ldsm4(sb + 3 * TB + off, bl);
#pragma unroll
                for (int mt = 0; mt < 2; mt++) {
                    mma16816(acc[mt][nt * 2],     ah[mt], bh[0], bh[1]);
                    mma16816(acc[mt][nt * 2 + 1], ah[mt], bh[2], bh[3]);
                    mma16816(acc[mt][nt * 2],     ah[mt], bl[0], bl[1]);
                    mma16816(acc[mt][nt * 2 + 1], ah[mt], bl[2], bl[3]);
                    mma16816(acc[mt][nt * 2],     al[mt], bh[0], bh[1]);
                    mma16816(acc[mt][nt * 2 + 1], al[mt], bh[2], bh[3]);
                }
            }
        }
    }

    const int erow = lane >> 2;
    const int ecol = (lane & 3) * 2;
#pragma unroll
    for (int mt = 0; mt < 2; mt++) {
#pragma unroll
        for (int nt8 = 0; nt8 < 8; nt8++) {
            long long row = m0 + wm * 32 + mt * 16 + erow;
            int col = n0 + wn * 64 + nt8 * 8 + ecol;
            float b0 = bias ? bias[col]     : 0.f;
            float b1 = bias ? bias[col + 1] : 0.f;
            float2 r0 = make_float2(acc[mt][nt8][0] + b0, acc[mt][nt8][1] + b1);
            float2 r1 = make_float2(acc[mt][nt8][2] + b0, acc[mt][nt8][3] + b1);
            *(float2*)(C + row * N + col)       = r0;
            *(float2*)(C + (row + 8) * N + col) = r1;
        }
    }
}

// ---------------------------------------------------------------------------
// Tensorized windowed attention: one CTA per (window, head), 128 threads.
// smem: Qh Ql Kh Kl Vth Vtl — six 64x64 bf16 tiles (128B rows, xor swizzle).
// 4 warps, each owns a 16-query strip:
//   S = Q K^T (3-term HMMA) -> softmax in registers (shfl over lane&3 group)
//   -> P converted reg->bf16 hi/lo A-frags -> O = P V (3-term HMMA, V^T smem)
// Epilogue writes bf16 hi/lo to feed the projection GEMM.
// ---------------------------------------------------------------------------
#define ATB 8192   // one 64x64 bf16 tile (64 rows x 128B)

__global__ __launch_bounds__(128, 4)
void attn_mma(const float* __restrict__ qkv,
              __nv_bfloat16* __restrict__ oh, __nv_bfloat16* __restrict__ ol)
{
    extern __shared__ char sm[];
    const uint32_t sb = smem_u32(sm);
    char* Qh = sm;
    char* Ql = sm + ATB;
    char* Kh = sm + 2 * ATB;
    char* Kl = sm + 3 * ATB;
    char* Vh = sm + 4 * ATB;
    char* Vl = sm + 5 * ATB;

    const int tid  = threadIdx.x;
    const int lane = tid & 31;
    const int wq   = tid >> 5;        // warp = 16-query strip
    const int h    = blockIdx.x;
    const int wb   = blockIdx.y;

    const float* base = qkv + (long long)wb * WINW * QKV_DIM + h * HD;

    // ---- load + split Q, K (row-major) and V (transposed) ----
#pragma unroll
    for (int i = 0; i < 4; i++) {
        int idx = tid + i * 128;          // 0..511: (row, chunk-of-8)
        int row = idx >> 3;
        int c   = idx & 7;
        const float* p = base + (long long)row * QKV_DIM + c * 8;
        uint32_t off = (uint32_t)(row * 128 + ((c ^ (row & 7)) << 4));
        // Q
        {
            float4 v0 = *(const float4*)(p);
            float4 v1 = *(const float4*)(p + 4);
            uint32_t H[4], L[4];
            split_pack(v0.x, v0.y, H[0], L[0]);
            split_pack(v0.z, v0.w, H[1], L[1]);
            split_pack(v1.x, v1.y, H[2], L[2]);
            split_pack(v1.z, v1.w, H[3], L[3]);
            *(uint4*)(Qh + off) = make_uint4(H[0], H[1], H[2], H[3]);
            *(uint4*)(Ql + off) = make_uint4(L[0], L[1], L[2], L[3]);
        }
        // K
        {
            float4 v0 = *(const float4*)(p + 512);
            float4 v1 = *(const float4*)(p + 516);
            uint32_t H[4], L[4];
            split_pack(v0.x, v0.y, H[0], L[0]);
            split_pack(v0.z, v0.w, H[1], L[1]);
            split_pack(v1.x, v1.y, H[2], L[2]);
            split_pack(v1.z, v1.w, H[3], L[3]);
            *(uint4*)(Kh + off) = make_uint4(H[0], H[1], H[2], H[3]);
            *(uint4*)(Kl + off) = make_uint4(L[0], L[1], L[2], L[3]);
        }
        // V: transpose into Vt[hd][token]
        {
            float4 v0 = *(const float4*)(p + 1024);
            float4 v1 = *(const float4*)(p + 1028);
            float f[8] = {v0.x, v0.y, v0.z, v0.w, v1.x, v1.y, v1.z, v1.w};
            int tok = row;
#pragma unroll
            for (int e = 0; e < 8; e++) {
                int hd = c * 8 + e;
                uint32_t toff = (uint32_t)(hd * 128 +
                                (((tok >> 3) ^ (hd & 7)) << 4) + (tok & 7) * 2);
                __nv_bfloat16 hh, ll;
                split1(f[e], hh, ll);
                *(__nv_bfloat16*)(Vh + toff) = hh;
                *(__nv_bfloat16*)(Vl + toff) = ll;
            }
        }
    }
    __syncthreads();

    const int arow = wq * 16 + (lane & 7) + ((lane >> 3) & 1) * 8;
    const int ac   = lane >> 4;
    const int brow = (lane & 7) + (lane >> 4) * 8;
    const int bc   = (lane >> 3) & 1;

    // ---- S = Q K^T : m16 x n64 x k64, 3-term split ----
    float s[8][4];
#pragma unroll
    for (int j = 0; j < 8; j++)
#pragma unroll
        for (int l = 0; l < 4; l++) s[j][l] = 0.f;

#pragma unroll
    for (int kk = 0; kk < 4; kk++) {
        uint32_t ah[4], al[4];
        {
            int r = arow;
            uint32_t off = (uint32_t)(r * 128 + (((2 * kk + ac) ^ (r & 7)) << 4));
            ldsm4(sb + off, ah);             // Qh
            ldsm4(sb + ATB + off, al);       // Ql
        }
#pragma unroll
        for (int nt = 0; nt < 4; nt++) {
            int r = brow + nt * 16;
            uint32_t off = (uint32_t)(r * 128 + (((2 * kk + bc) ^ (r & 7)) << 4));
            uint32_t bh[4], bl[4];
            ldsm4(sb + 2 * ATB + off, bh);   // Kh
            ldsm4(sb + 3 * ATB + off, bl);   // Kl
            mma16816(s[nt * 2],     ah, bh[0], bh[1]);
            mma16816(s[nt * 2 + 1], ah, bh[2], bh[3]);
            mma16816(s[nt * 2],     ah, bl[0], bl[1]);
            mma16816(s[nt * 2 + 1], ah, bl[2], bl[3]);
            mma16816(s[nt * 2],     al, bh[0], bh[1]);
            mma16816(s[nt * 2 + 1], al, bh[2], bh[3]);
        }
    }

    // ---- softmax in registers (rows: lane>>2 and lane>>2 + 8) ----
    float mx0 = -1e30f, mx1 = -1e30f;
#pragma unroll
    for (int j = 0; j < 8; j++) {
        mx0 = fmaxf(mx0, fmaxf(s[j][0], s[j][1]));
        mx1 = fmaxf(mx1, fmaxf(s[j][2], s[j][3]));
    }
    mx0 = fmaxf(mx0, __shfl_xor_sync(0xffffffffu, mx0, 1));
    mx0 = fmaxf(mx0, __shfl_xor_sync(0xffffffffu, mx0, 2));
    mx1 = fmaxf(mx1, __shfl_xor_sync(0xffffffffu, mx1, 1));
    mx1 = fmaxf(mx1, __shfl_xor_sync(0xffffffffu, mx1, 2));

    float sum0 = 0.f, sum1 = 0.f;
#pragma unroll
    for (int j = 0; j < 8; j++) {
        s[j][0] = fexp(0.125f * (s[j][0] - mx0));
        s[j][1] = fexp(0.125f * (s[j][1] - mx0));
        s[j][2] = fexp(0.125f * (s[j][2] - mx1));
        s[j][3] = fexp(0.125f * (s[j][3] - mx1));
        sum0 += s[j][0] + s[j][1];
        sum1 += s[j][2] + s[j][3];
    }
    sum0 += __shfl_xor_sync(0xffffffffu, sum0, 1);
    sum0 += __shfl_xor_sync(0xffffffffu, sum0, 2);
    sum1 += __shfl_xor_sync(0xffffffffu, sum1, 1);
    sum1 += __shfl_xor_sync(0xffffffffu, sum1, 2);
    const float inv0 = 1.0f / sum0;
    const float inv1 = 1.0f / sum1;

    // ---- O = P V : m16 x n64 x k64, P from registers, 3-term split ----
    float o[8][4];
#pragma unroll
    for (int j = 0; j < 8; j++)
#pragma unroll
        for (int l = 0; l < 4; l++) o[j][l] = 0.f;

#pragma unroll
    for (int j = 0; j < 4; j++) {        // k-step: keys 16j..16j+15
        uint32_t ph[4], pl[4];
        split_pack(s[2 * j][0],     s[2 * j][1],     ph[0], pl[0]);
        split_pack(s[2 * j][2],     s[2 * j][3],     ph[1], pl[1]);
        split_pack(s[2 * j + 1][0], s[2 * j + 1][1], ph[2], pl[2]);
        split_pack(s[2 * j + 1][2], s[2 * j + 1][3], ph[3], pl[3]);
#pragma unroll
        for (int nt = 0; nt < 4; nt++) {
            int r = brow + nt * 16;      // Vt row = hd index
            uint32_t off = (uint32_t)(r * 128 + (((2 * j + bc) ^ (r & 7)) << 4));
            uint32_t bh[4], bl[4];
            ldsm4(sb + 4 * ATB + off, bh);   // Vh
            ldsm4(sb + 5 * ATB + off, bl);   // Vl
            mma16816(o[nt * 2],     ph, bh[0], bh[1]);
            mma16816(o[nt * 2 + 1], ph, bh[2], bh[3]);
            mma16816(o[nt * 2],     ph, bl[0], bl[1]);
            mma16816(o[nt * 2 + 1], ph, bl[2], bl[3]);
            mma16816(o[nt * 2],     pl, bh[0], bh[1]);
            mma16816(o[nt * 2 + 1], pl, bh[2], bh[3]);
        }
    }

    // ---- epilogue: normalize, split, store bf16 hi/lo ----
    const long long row0 = (long long)wb * WINW + wq * 16 + (lane >> 2);
    const int colb = h * HD + (lane & 3) * 2;
#pragma unroll
    for (int j = 0; j < 8; j++) {
        int col = colb + j * 8;
        uint32_t H, L;
        split_pack(o[j][0] * inv0, o[j][1] * inv0, H, L);
        *(uint32_t*)(oh + row0 * C_DIM + col) = H;
        *(uint32_t*)(ol + row0 * C_DIM + col) = L;
        split_pack(o[j][2] * inv1, o[j][3] * inv1, H, L);
        *(uint32_t*)(oh + (row0 + 8) * C_DIM + col) = H;
        *(uint32_t*)(ol + (row0 + 8) * C_DIM + col) = L;
    }
}

// ---------------------------------------------------------------------------
extern "C" void kernel_launch(void* const* d_in, const int* in_sizes, int n_in,
                              void* d_out, int out_size)
{
    const float* x      = (const float*)d_in[0];
    const float* qkv_w  = (const float*)d_in[1];
    const float* proj_w = (const float*)d_in[2];
    const float* proj_b = (const float*)d_in[3];
    float* out = (float*)d_out;

    float *qkv_buf = nullptr;
    __nv_bfloat16 *xh, *xl, *ath, *atl, *wqh, *wql, *wph, *wpl;
    cudaGetSymbolAddress((void**)&qkv_buf, g_qkv);
    cudaGetSymbolAddress((void**)&xh,  g_xh);
    cudaGetSymbolAddress((void**)&xl,  g_xl);
    cudaGetSymbolAddress((void**)&ath, g_ath);
    cudaGetSymbolAddress((void**)&atl, g_atl);
    cudaGetSymbolAddress((void**)&wqh, g_wqh);
    cudaGetSymbolAddress((void**)&wql, g_wql);
    cudaGetSymbolAddress((void**)&wph, g_wph);
    cudaGetSymbolAddress((void**)&wpl, g_wpl);

    const int gemm_smem = 4 * TB;     // 64 KB
    const int attn_smem = 6 * ATB;    // 48 KB
    cudaFuncSetAttribute(gemm_split, cudaFuncAttributeMaxDynamicSharedMemorySize,
                         gemm_smem);
    cudaFuncSetAttribute(attn_mma, cudaFuncAttributeMaxDynamicSharedMemorySize,
                         attn_smem);

    // 0) split inputs to bf16 hi/lo
    {
        long long nx = (long long)M_ROWS * C_DIM;
        split_f32<<<(unsigned)((nx / 8 + 255) / 256), 256>>>(x, xh, xl, nx);
        long long nq = (long long)QKV_DIM * C_DIM;
        split_f32<<<(unsigned)((nq / 8 + 255) / 256), 256>>>(qkv_w, wqh, wql, nq);
        long long np = (long long)C_DIM * C_DIM;
        split_f32<<<(unsigned)((np / 8 + 255) / 256), 256>>>(proj_w, wph, wpl, np);
    }

    // 1) QKV projection
    gemm_split<<<dim3(QKV_DIM / 128, M_ROWS / 128), 256, gemm_smem>>>(
        xh, xl, wqh, wql, nullptr, qkv_buf, M_ROWS, QKV_DIM, C_DIM);

    // 2) Tensorized windowed attention (emits bf16 hi/lo)
    attn_mma<<<dim3(NH, NWIN), 128, attn_smem>>>(qkv_buf, ath, atl);

    // 3) Output projection (+bias)
    gemm_split<<<dim3(C_DIM / 128, M_ROWS / 128), 256, gemm_smem>>>(
        ath, atl, wph, wpl, proj_b, out, M_ROWS, C_DIM, C_DIM);
}

// round 13
// speedup vs baseline: 1.9041x; 1.3580x over previous
#include <cuda_runtime.h>
#include <cuda_fp16.h>
#include <cstdint>

// ---------------------------------------------------------------------------
// x[65536,512] -> qkv = x @ qkv_w^T -> windowed attn (1024x8, 64x64x64)
//   -> out = att @ proj_w^T + b
// GEMMs: HMMA fp16 2-term split: C = (Ah+Al)*Bh = A*B_hi exactly; only the
// Sigma a*b_lo term (RMS ~2.8e-4 rel) is dropped. 33% fewer MMAs than the
// 3-term bf16 scheme, B-lo tiles eliminated from smem entirely.
// ---------------------------------------------------------------------------

#define M_ROWS   65536
#define C_DIM    512
#define QKV_DIM  1536
#define NH       8
#define HD       64
#define WINW     64
#define NWIN     1024

__device__ float  g_qkv[(long long)M_ROWS * QKV_DIM];
__device__ __half g_xh [(long long)M_ROWS * C_DIM];
__device__ __half g_xl [(long long)M_ROWS * C_DIM];
__device__ __half g_ath[(long long)M_ROWS * C_DIM];
__device__ __half g_atl[(long long)M_ROWS * C_DIM];
__device__ __half g_wqh[QKV_DIM * C_DIM];
__device__ __half g_wql[QKV_DIM * C_DIM];
__device__ __half g_wph[C_DIM * C_DIM];
__device__ __half g_wpl[C_DIM * C_DIM];

// ------------------------------ helpers ------------------------------------
__device__ __forceinline__ uint32_t smem_u32(const void* p) {
    uint32_t a;
    asm("{ .reg .u64 t; cvta.to.shared.u64 t, %1; cvt.u32.u64 %0, t; }"
        : "=r"(a) : "l"(p));
    return a;
}
__device__ __forceinline__ void ldsm4(uint32_t addr, uint32_t r[4]) {
    asm volatile("ldmatrix.sync.aligned.m8n8.x4.shared.b16 {%0,%1,%2,%3}, [%4];"
                 : "=r"(r[0]), "=r"(r[1]), "=r"(r[2]), "=r"(r[3]) : "r"(addr));
}
__device__ __forceinline__ void mma16816(float d[4], const uint32_t a[4],
                                         const uint32_t b0, const uint32_t b1) {
    asm volatile(
        "mma.sync.aligned.m16n8k16.row.col.f32.f16.f16.f32 "
        "{%0,%1,%2,%3},{%4,%5,%6,%7},{%8,%9},{%0,%1,%2,%3};"
        : "+f"(d[0]), "+f"(d[1]), "+f"(d[2]), "+f"(d[3])
        : "r"(a[0]), "r"(a[1]), "r"(a[2]), "r"(a[3]), "r"(b0), "r"(b1));
}
__device__ __forceinline__ void cp16(uint32_t saddr, const void* gaddr) {
    asm volatile("cp.async.cg.shared.global [%0], [%1], 16;"
                 :: "r"(saddr), "l"(gaddr));
}
#define CP_COMMIT() asm volatile("cp.async.commit_group;" ::: "memory")
#define CP_WAIT0()  asm volatile("cp.async.wait_group 0;" ::: "memory")

__device__ __forceinline__ uint32_t pack2(__half a, __half b) {
    return ((uint32_t)__half_as_ushort(b) << 16) | __half_as_ushort(a);
}
__device__ __forceinline__ void split1(float v, __half& h, __half& l) {
    h = __float2half_rn(v);
    l = __float2half_rn(v - __half2float(h));
}
__device__ __forceinline__ void split_pack(float x, float y,
                                           uint32_t& hh, uint32_t& ll) {
    __half h0, l0, h1, l1;
    split1(x, h0, l0);
    split1(y, h1, l1);
    hh = pack2(h0, h1);
    ll = pack2(l0, l1);
}

// Fast e^x on the FMA pipe (x <= 0). |err| ~ 1e-7 rel.
__device__ __forceinline__ float fexp(float x) {
    float y = fmaxf(x * 1.4426950408889634f, -120.f);
    float t = y + 12582912.f;
    int   ki = __float_as_int(t) - 0x4b400000;
    float f = y - (t - 12582912.f);
    float p = 1.3333558146e-3f;
    p = fmaf(p, f, 9.6181291071e-3f);
    p = fmaf(p, f, 5.5504108664e-2f);
    p = fmaf(p, f, 2.4022650695e-1f);
    p = fmaf(p, f, 6.9314718056e-1f);
    p = fmaf(p, f, 1.0f);
    return __int_as_float(__float_as_int(p) + (ki << 23));
}

// ---------------------------------------------------------------------------
// Split pass: fp32 [n] -> fp16 hi[n] + lo[n]
// ---------------------------------------------------------------------------
__global__ void split_f32(const float* __restrict__ src,
                          __half* __restrict__ hi,
                          __half* __restrict__ lo, long long n)
{
    long long i = ((long long)blockIdx.x * blockDim.x + threadIdx.x) * 8;
    if (i >= n) return;
    float4 v0 = *(const float4*)(src + i);
    float4 v1 = *(const float4*)(src + i + 4);
    float f[8] = {v0.x, v0.y, v0.z, v0.w, v1.x, v1.y, v1.z, v1.w};
    uint32_t H[4], L[4];
#pragma unroll
    for (int j = 0; j < 4; j++)
        split_pack(f[2 * j], f[2 * j + 1], H[j], L[j]);
    *(uint4*)(hi + i) = make_uint4(H[0], H[1], H[2], H[3]);
    *(uint4*)(lo + i) = make_uint4(L[0], L[1], L[2], L[3]);
}

// ---------------------------------------------------------------------------
// HMMA GEMM (NT), fp16 2-term: C = Ah*Bh + Al*Bh (+bias), fp32 out.
// CTA 128x128, BK=64. smem: 3 tiles (Ah,Al,Bh) of 128 rows x 128B, xor
// swizzle per 16B chunk. Fill via cp.async.cg. 8 warps = 4(M) x 2(N).
// ---------------------------------------------------------------------------
#define TB 16384

__global__ __launch_bounds__(256, 2)
void gemm_split(const __half* __restrict__ Ah,
                const __half* __restrict__ Al,
                const __half* __restrict__ Bh,
                const float* __restrict__ bias, float* __restrict__ C,
                int M, int N, int K)
{
    extern __shared__ char sm[];
    const uint32_t sb = smem_u32(sm);

    const int tid  = threadIdx.x;
    const int lane = tid & 31;
    const int wid  = tid >> 5;
    const int wm   = wid & 3;
    const int wn   = wid >> 2;
    const long long m0 = (long long)blockIdx.y * 128;
    const int n0 = blockIdx.x * 128;

    float acc[2][8][4];
#pragma unroll
    for (int i = 0; i < 2; i++)
#pragma unroll
        for (int j = 0; j < 8; j++)
#pragma unroll
            for (int l = 0; l < 4; l++) acc[i][j][l] = 0.f;

    const int arow0 = wm * 32 + (lane & 7) + ((lane >> 3) & 1) * 8;
    const int ac    = lane >> 4;
    const int brow0 = wn * 64 + (lane & 7) + (lane >> 4) * 8;
    const int bc    = (lane >> 3) & 1;

    const int frow = tid >> 3;
    const int fc   = tid & 7;

    const int NCH = K >> 6;
    for (int ch = 0; ch < NCH; ch++) {
        __syncthreads();
#pragma unroll
        for (int i = 0; i < 4; i++) {
            int row = frow + i * 32;
            uint32_t off = (uint32_t)(row * 128 + ((fc ^ (row & 7)) << 4));
            long long ga = (m0 + row) * K + ch * 64 + fc * 8;
            long long gb = (long long)(n0 + row) * K + ch * 64 + fc * 8;
            cp16(sb + off,          Ah + ga);
            cp16(sb + TB + off,     Al + ga);
            cp16(sb + 2 * TB + off, Bh + gb);
        }
        CP_COMMIT();
        CP_WAIT0();
        __syncthreads();

#pragma unroll
        for (int kk = 0; kk < 4; kk++) {
            uint32_t ah[2][4], al[2][4];
#pragma unroll
            for (int mt = 0; mt < 2; mt++) {
                int r = arow0 + mt * 16;
                uint32_t off = (uint32_t)(r * 128 + (((2 * kk + ac) ^ (r & 7)) << 4));
                ldsm4(sb + off, ah[mt]);
                ldsm4(sb + TB + off, al[mt]);
            }
#pragma unroll
            for (int nt = 0; nt < 4; nt++) {
                int r = brow0 + nt * 16;
                uint32_t off = (uint32_t)(r * 128 + (((2 * kk + bc) ^ (r & 7)) << 4));
                uint32_t bh[4];
                ldsm4(sb + 2 * TB + off, bh);
#pragma unroll
                for (int mt = 0; mt < 2; mt++) {
                    mma16816(acc[mt][nt * 2],     ah[mt], bh[0], bh[1]);
                    mma16816(acc[mt][nt * 2 + 1], ah[mt], bh[2], bh[3]);
                    mma16816(acc[mt][nt * 2],     al[mt], bh[0], bh[1]);
                    mma16816(acc[mt][nt * 2 + 1], al[mt], bh[2], bh[3]);
                }
            }
        }
    }

    const int erow = lane >> 2;
    const int ecol = (lane & 3) * 2;
#pragma unroll
    for (int mt = 0; mt < 2; mt++) {
#pragma unroll
        for (int nt8 = 0; nt8 < 8; nt8++) {
            long long row = m0 + wm * 32 + mt * 16 + erow;
            int col = n0 + wn * 64 + nt8 * 8 + ecol;
            float b0 = bias ? bias[col]     : 0.f;
            float b1 = bias ? bias[col + 1] : 0.f;
            float2 r0 = make_float2(acc[mt][nt8][0] + b0, acc[mt][nt8][1] + b1);
            float2 r1 = make_float2(acc[mt][nt8][2] + b0, acc[mt][nt8][3] + b1);
            *(float2*)(C + row * N + col)       = r0;
            *(float2*)(C + (row + 8) * N + col) = r1;
        }
    }
}

// ---------------------------------------------------------------------------
// Tensorized windowed attention, fp16 2-term: one CTA per (window, head).
// smem: Qh Ql Kh Vth — four 64x64 fp16 tiles (128B rows, xor swizzle).
//   S = (Qh+Ql) K_hi^T -> softmax in regs -> O = (Ph+Pl) V_hi
// Epilogue writes fp16 hi/lo for the projection GEMM.
// ---------------------------------------------------------------------------
#define ATB 8192

__global__ __launch_bounds__(128, 4)
void attn_mma(const float* __restrict__ qkv,
              __half* __restrict__ oh, __half* __restrict__ ol)
{
    extern __shared__ char sm[];
    const uint32_t sb = smem_u32(sm);
    char* Qh = sm;
    char* Ql = sm + ATB;
    char* Kh = sm + 2 * ATB;
    char* Vh = sm + 3 * ATB;

    const int tid  = threadIdx.x;
    const int lane = tid & 31;
    const int wq   = tid >> 5;
    const int h    = blockIdx.x;
    const int wb   = blockIdx.y;

    const float* base = qkv + (long long)wb * WINW * QKV_DIM + h * HD;

    // ---- load + split Q (hi/lo), K hi, V hi (transposed) ----
#pragma unroll
    for (int i = 0; i < 4; i++) {
        int idx = tid + i * 128;
        int row = idx >> 3;
        int c   = idx & 7;
        const float* p = base + (long long)row * QKV_DIM + c * 8;
        uint32_t off = (uint32_t)(row * 128 + ((c ^ (row & 7)) << 4));
        // Q hi + lo
        {
            float4 v0 = *(const float4*)(p);
            float4 v1 = *(const float4*)(p + 4);
            uint32_t H[4], L[4];
            split_pack(v0.x, v0.y, H[0], L[0]);
            split_pack(v0.z, v0.w, H[1], L[1]);
            split_pack(v1.x, v1.y, H[2], L[2]);
            split_pack(v1.z, v1.w, H[3], L[3]);
            *(uint4*)(Qh + off) = make_uint4(H[0], H[1], H[2], H[3]);
            *(uint4*)(Ql + off) = make_uint4(L[0], L[1], L[2], L[3]);
        }
        // K hi
        {
            float4 v0 = *(const float4*)(p + 512);
            float4 v1 = *(const float4*)(p + 516);
            uint32_t H[4];
            H[0] = pack2(__float2half_rn(v0.x), __float2half_rn(v0.y));
            H[1] = pack2(__float2half_rn(v0.z), __float2half_rn(v0.w));
            H[2] = pack2(__float2half_rn(v1.x), __float2half_rn(v1.y));
            H[3] = pack2(__float2half_rn(v1.z), __float2half_rn(v1.w));
            *(uint4*)(Kh + off) = make_uint4(H[0], H[1], H[2], H[3]);
        }
        // V hi, transposed into Vt[hd][token]
        {
            float4 v0 = *(const float4*)(p + 1024);
            float4 v1 = *(const float4*)(p + 1028);
            float f[8] = {v0.x, v0.y, v0.z, v0.w, v1.x, v1.y, v1.z, v1.w};
            int tok = row;
#pragma unroll
            for (int e = 0; e < 8; e++) {
                int hd = c * 8 + e;
                uint32_t toff = (uint32_t)(hd * 128 +
                                (((tok >> 3) ^ (hd & 7)) << 4) + (tok & 7) * 2);
                *(__half*)(Vh + toff) = __float2half_rn(f[e]);
            }
        }
    }
    __syncthreads();

    const int arow = wq * 16 + (lane & 7) + ((lane >> 3) & 1) * 8;
    const int ac   = lane >> 4;
    const int brow = (lane & 7) + (lane >> 4) * 8;
    const int bc   = (lane >> 3) & 1;

    // ---- S = Q K_hi^T : m16 x n64 x k64, 2-term ----
    float s[8][4];
#pragma unroll
    for (int j = 0; j < 8; j++)
#pragma unroll
        for (int l = 0; l < 4; l++) s[j][l] = 0.f;

#pragma unroll
    for (int kk = 0; kk < 4; kk++) {
        uint32_t ah[4], al[4];
        {
            int r = arow;
            uint32_t off = (uint32_t)(r * 128 + (((2 * kk + ac) ^ (r & 7)) << 4));
            ldsm4(sb + off, ah);
            ldsm4(sb + ATB + off, al);
        }
#pragma unroll
        for (int nt = 0; nt < 4; nt++) {
            int r = brow + nt * 16;
            uint32_t off = (uint32_t)(r * 128 + (((2 * kk + bc) ^ (r & 7)) << 4));
            uint32_t bh[4];
            ldsm4(sb + 2 * ATB + off, bh);
            mma16816(s[nt * 2],     ah, bh[0], bh[1]);
            mma16816(s[nt * 2 + 1], ah, bh[2], bh[3]);
            mma16816(s[nt * 2],     al, bh[0], bh[1]);
            mma16816(s[nt * 2 + 1], al, bh[2], bh[3]);
        }
    }

    // ---- softmax in registers ----
    float mx0 = -1e30f, mx1 = -1e30f;
#pragma unroll
    for (int j = 0; j < 8; j++) {
        mx0 = fmaxf(mx0, fmaxf(s[j][0], s[j][1]));
        mx1 = fmaxf(mx1, fmaxf(s[j][2], s[j][3]));
    }
    mx0 = fmaxf(mx0, __shfl_xor_sync(0xffffffffu, mx0, 1));
    mx0 = fmaxf(mx0, __shfl_xor_sync(0xffffffffu, mx0, 2));
    mx1 = fmaxf(mx1, __shfl_xor_sync(0xffffffffu, mx1, 1));
    mx1 = fmaxf(mx1, __shfl_xor_sync(0xffffffffu, mx1, 2));

    float sum0 = 0.f, sum1 = 0.f;
#pragma unroll
    for (int j = 0; j < 8; j++) {
        s[j][0] = fexp(0.125f * (s[j][0] - mx0));
        s[j][1] = fexp(0.125f * (s[j][1] - mx0));
        s[j][2] = fexp(0.125f * (s[j][2] - mx1));
        s[j][3] = fexp(0.125f * (s[j][3] - mx1));
        sum0 += s[j][0] + s[j][1];
        sum1 += s[j][2] + s[j][3];
    }
    sum0 += __shfl_xor_sync(0xffffffffu, sum0, 1);
    sum0 += __shfl_xor_sync(0xffffffffu, sum0, 2);
    sum1 += __shfl_xor_sync(0xffffffffu, sum1, 1);
    sum1 += __shfl_xor_sync(0xffffffffu, sum1, 2);
    const float inv0 = 1.0f / sum0;
    const float inv1 = 1.0f / sum1;

    // ---- O = P V_hi : m16 x n64 x k64, P split 2-term from registers ----
    float o[8][4];
#pragma unroll
    for (int j = 0; j < 8; j++)
#pragma unroll
        for (int l = 0; l < 4; l++) o[j][l] = 0.f;

#pragma unroll
    for (int j = 0; j < 4; j++) {
        uint32_t ph[4], pl[4];
        split_pack(s[2 * j][0],     s[2 * j][1],     ph[0], pl[0]);
        split_pack(s[2 * j][2],     s[2 * j][3],     ph[1], pl[1]);
        split_pack(s[2 * j + 1][0], s[2 * j + 1][1], ph[2], pl[2]);
        split_pack(s[2 * j + 1][2], s[2 * j + 1][3], ph[3], pl[3]);
#pragma unroll
        for (int nt = 0; nt < 4; nt++) {
            int r = brow + nt * 16;
            uint32_t off = (uint32_t)(r * 128 + (((2 * j + bc) ^ (r & 7)) << 4));
            uint32_t bh[4];
            ldsm4(sb + 3 * ATB + off, bh);
            mma16816(o[nt * 2],     ph, bh[0], bh[1]);
            mma16816(o[nt * 2 + 1], ph, bh[2], bh[3]);
            mma16816(o[nt * 2],     pl, bh[0], bh[1]);
            mma16816(o[nt * 2 + 1], pl, bh[2], bh[3]);
        }
    }

    // ---- epilogue: normalize, split, store fp16 hi/lo ----
    const long long row0 = (long long)wb * WINW + wq * 16 + (lane >> 2);
    const int colb = h * HD + (lane & 3) * 2;
#pragma unroll
    for (int j = 0; j < 8; j++) {
        int col = colb + j * 8;
        uint32_t H, L;
        split_pack(o[j][0] * inv0, o[j][1] * inv0, H, L);
        *(uint32_t*)(oh + row0 * C_DIM + col) = H;
        *(uint32_t*)(ol + row0 * C_DIM + col) = L;
        split_pack(o[j][2] * inv1, o[j][3] * inv1, H, L);
        *(uint32_t*)(oh + (row0 + 8) * C_DIM + col) = H;
        *(uint32_t*)(ol + (row0 + 8) * C_DIM + col) = L;
    }
}

// ---------------------------------------------------------------------------
extern "C" void kernel_launch(void* const* d_in, const int* in_sizes, int n_in,
                              void* d_out, int out_size)
{
    const float* x      = (const float*)d_in[0];
    const float* qkv_w  = (const float*)d_in[1];
    const float* proj_w = (const float*)d_in[2];
    const float* proj_b = (const float*)d_in[3];
    float* out = (float*)d_out;

    float* qkv_buf = nullptr;
    __half *xh, *xl, *ath, *atl, *wqh, *wql, *wph, *wpl;
    cudaGetSymbolAddress((void**)&qkv_buf, g_qkv);
    cudaGetSymbolAddress((void**)&xh,  g_xh);
    cudaGetSymbolAddress((void**)&xl,  g_xl);
    cudaGetSymbolAddress((void**)&ath, g_ath);
    cudaGetSymbolAddress((void**)&atl, g_atl);
    cudaGetSymbolAddress((void**)&wqh, g_wqh);
    cudaGetSymbolAddress((void**)&wql, g_wql);
    cudaGetSymbolAddress((void**)&wph, g_wph);
    cudaGetSymbolAddress((void**)&wpl, g_wpl);

    const int gemm_smem = 3 * TB;     // 48 KB
    const int attn_smem = 4 * ATB;    // 32 KB
    cudaFuncSetAttribute(gemm_split, cudaFuncAttributeMaxDynamicSharedMemorySize,
                         gemm_smem);
    cudaFuncSetAttribute(attn_mma, cudaFuncAttributeMaxDynamicSharedMemorySize,
                         attn_smem);

    // 0) split inputs to fp16 hi/lo (weights: only hi is consumed by GEMMs)
    {
        long long nx = (long long)M_ROWS * C_DIM;
        split_f32<<<(unsigned)((nx / 8 + 255) / 256), 256>>>(x, xh, xl, nx);
        long long nq = (long long)QKV_DIM * C_DIM;
        split_f32<<<(unsigned)((nq / 8 + 255) / 256), 256>>>(qkv_w, wqh, wql, nq);
        long long np = (long long)C_DIM * C_DIM;
        split_f32<<<(unsigned)((np / 8 + 255) / 256), 256>>>(proj_w, wph, wpl, np);
    }

    // 1) QKV projection
    gemm_split<<<dim3(QKV_DIM / 128, M_ROWS / 128), 256, gemm_smem>>>(
        xh, xl, wqh, nullptr, qkv_buf, M_ROWS, QKV_DIM, C_DIM);

    // 2) Tensorized windowed attention (emits fp16 hi/lo)
    attn_mma<<<dim3(NH, NWIN), 128, attn_smem>>>(qkv_buf, ath, atl);

    // 3) Output projection (+bias)
    gemm_split<<<dim3(C_DIM / 128, M_ROWS / 128), 256, gemm_smem>>>(
        ath, atl, wph, proj_b, out, M_ROWS, C_DIM, C_DIM);
}